// round 3
// baseline (speedup 1.0000x reference)
#include <cuda_runtime.h>
#include <math.h>

#define NUSERS 50000
#define NITEMS 20000
#define NNODES 70000
#define FDIM   768
#define H1D    512
#define HID    128
#define NEDGE  2000000
#define ALPHA  0.25f
#define LN_EPS 1e-5f

// ---------------- scratch (static device allocations: allowed) ----------------
__device__ float g_t1[(size_t)NITEMS * H1D];   // 41 MB
__device__ float g_t2[(size_t)NITEMS * HID];   // 10 MB
__device__ float g_t3[(size_t)NITEMS * HID];   // 10 MB
__device__ float g_xa[(size_t)NNODES * HID];   // 36 MB
__device__ float g_xb[(size_t)NNODES * HID];   // 36 MB
__device__ float g_dinv[NNODES];
__device__ int   g_deg[NNODES];
__device__ float g_en[NEDGE];                  // 8 MB

// ---------------- SGEMM: C = A[M,K] @ B[K,N] + bias ----------------
// BM=BN=128, BK=16, 256 threads, 8x8 per thread. K,N assumed multiples of 16/128.
__global__ void sgemm_bias(const float* __restrict__ A, const float* __restrict__ B,
                           const float* __restrict__ bias, float* __restrict__ C,
                           int M, int N, int K)
{
    const int BM = 128, BN = 128, BK = 16;
    __shared__ float As[BK][BM];
    __shared__ float Bs[BK][BN];

    int tid = threadIdx.x;
    int tx = tid & 15;          // 0..15 -> N
    int ty = tid >> 4;          // 0..15 -> M
    int row0 = blockIdx.y * BM;
    int col0 = blockIdx.x * BN;

    float acc[8][8];
#pragma unroll
    for (int i = 0; i < 8; i++)
#pragma unroll
        for (int j = 0; j < 8; j++) acc[i][j] = 0.f;

    for (int k0 = 0; k0 < K; k0 += BK) {
#pragma unroll
        for (int it = 0; it < 2; ++it) {
            int idx = tid + it * 256;                 // 0..511
            // A tile: 128 rows x 4 float4
            int ar = idx >> 2, ac = (idx & 3) * 4;
            int gr = row0 + ar;
            float4 av = make_float4(0.f, 0.f, 0.f, 0.f);
            if (gr < M) av = *(const float4*)(A + (size_t)gr * K + k0 + ac);
            As[ac + 0][ar] = av.x; As[ac + 1][ar] = av.y;
            As[ac + 2][ar] = av.z; As[ac + 3][ar] = av.w;
            // B tile: 16 rows x 32 float4
            int br = idx >> 5, bc = (idx & 31) * 4;
            float4 bv = *(const float4*)(B + (size_t)(k0 + br) * N + col0 + bc);
            *(float4*)&Bs[br][bc] = bv;
        }
        __syncthreads();

#pragma unroll
        for (int k = 0; k < BK; k++) {
            float a[8], b[8];
            *(float4*)&a[0] = *(float4*)&As[k][ty * 8];
            *(float4*)&a[4] = *(float4*)&As[k][ty * 8 + 4];
            *(float4*)&b[0] = *(float4*)&Bs[k][tx * 8];
            *(float4*)&b[4] = *(float4*)&Bs[k][tx * 8 + 4];
#pragma unroll
            for (int i = 0; i < 8; i++)
#pragma unroll
                for (int j = 0; j < 8; j++) acc[i][j] += a[i] * b[j];
        }
        __syncthreads();
    }

#pragma unroll
    for (int i = 0; i < 8; i++) {
        int gr = row0 + ty * 8 + i;
        if (gr >= M) continue;
#pragma unroll
        for (int j = 0; j < 8; j += 4) {
            int gc = col0 + tx * 8 + j;
            float4 cv;
            cv.x = acc[i][j + 0] + bias[gc + 0];
            cv.y = acc[i][j + 1] + bias[gc + 1];
            cv.z = acc[i][j + 2] + bias[gc + 2];
            cv.w = acc[i][j + 3] + bias[gc + 3];
            *(float4*)(C + (size_t)gr * N + gc) = cv;
        }
    }
}

// ---------------- LayerNorm + ReLU (in place), one block (128 thr) per row ----
template <int W>
__global__ void ln_relu(float* __restrict__ x, const float* __restrict__ g,
                        const float* __restrict__ be)
{
    constexpr int VPT = W / 128;
    int row = blockIdx.x;
    int tid = threadIdx.x;
    float* xr = x + (size_t)row * W;

    float v[VPT];
    float s = 0.f, s2 = 0.f;
#pragma unroll
    for (int i = 0; i < VPT; i++) {
        v[i] = xr[i * 128 + tid];
        s += v[i]; s2 += v[i] * v[i];
    }
#pragma unroll
    for (int o = 16; o > 0; o >>= 1) {
        s  += __shfl_xor_sync(0xffffffffu, s,  o);
        s2 += __shfl_xor_sync(0xffffffffu, s2, o);
    }
    __shared__ float rs[4], rs2[4];
    if ((tid & 31) == 0) { rs[tid >> 5] = s; rs2[tid >> 5] = s2; }
    __syncthreads();
    s  = rs[0] + rs[1] + rs[2] + rs[3];
    s2 = rs2[0] + rs2[1] + rs2[2] + rs2[3];

    float mu  = s / W;
    float var = s2 / W - mu * mu;
    float inv = 1.f / sqrtf(var + LN_EPS);
#pragma unroll
    for (int i = 0; i < VPT; i++) {
        int c = i * 128 + tid;
        float y = (v[i] - mu) * inv * g[c] + be[c];
        xr[c] = fmaxf(y, 0.f);
    }
}

// ---------------- build e0: x = emb (+ mw * normalize(t3)); out = alpha*x; zero xb
__global__ void build_e0(const float* __restrict__ emb, const float* __restrict__ mw,
                         float* __restrict__ out)
{
    int node = blockIdx.x;
    int tid = threadIdx.x;   // 128
    float x = emb[(size_t)node * HID + tid];
    if (node >= NUSERS) {
        int it = node - NUSERS;
        float h = g_t3[(size_t)it * HID + tid];
        float s2 = h * h;
#pragma unroll
        for (int o = 16; o > 0; o >>= 1) s2 += __shfl_xor_sync(0xffffffffu, s2, o);
        __shared__ float red[4];
        if ((tid & 31) == 0) red[tid >> 5] = s2;
        __syncthreads();
        float nrm = sqrtf(red[0] + red[1] + red[2] + red[3]);
        x += mw[0] * h / fmaxf(nrm, 1e-12f);
    }
    size_t o = (size_t)node * HID + tid;
    g_xa[o] = x;
    g_xb[o] = 0.f;
    out[o] = ALPHA * x;
}

// ---------------- degree / normalization ----------------
__global__ void zero_deg()
{
    int n = blockIdx.x * blockDim.x + threadIdx.x;
    if (n < NNODES) g_deg[n] = 0;
}

__global__ void deg_count(const int* __restrict__ dst)
{
    int e = blockIdx.x * blockDim.x + threadIdx.x;
    if (e < NEDGE) atomicAdd(&g_deg[dst[e]], 1);
}

__global__ void dinv_k()
{
    int n = blockIdx.x * blockDim.x + threadIdx.x;
    if (n < NNODES) {
        int d = g_deg[n];
        g_dinv[n] = (d > 0) ? (1.f / sqrtf((float)d)) : 0.f;
    }
}

__global__ void edge_norm(const int* __restrict__ src, const int* __restrict__ dst)
{
    int e = blockIdx.x * blockDim.x + threadIdx.x;
    if (e < NEDGE) g_en[e] = g_dinv[src[e]] * g_dinv[dst[e]];
}

// ---------------- propagate: one warp per edge, float4 vector reductions ------
__global__ void propagate(const int* __restrict__ src, const int* __restrict__ dst,
                          const float* __restrict__ xin, float* __restrict__ xout)
{
    int warp = (blockIdx.x * blockDim.x + threadIdx.x) >> 5;
    int lane = threadIdx.x & 31;
    if (warp >= NEDGE) return;
    int s = src[warp];
    int d = dst[warp];
    float n = g_en[warp];
    float4 v = *(const float4*)(xin + (size_t)s * HID + lane * 4);
    v.x *= n; v.y *= n; v.z *= n; v.w *= n;
    atomicAdd((float4*)(xout + (size_t)d * HID + lane * 4), v);  // RED.128 (sm_90+)
}

// ---------------- out += alpha * xnew; zero xold (next layer's target) --------
__global__ void axpy_zero(float* __restrict__ out, const float* __restrict__ xnew,
                          float* __restrict__ xold)
{
    int i = blockIdx.x * blockDim.x + threadIdx.x;
    const int NV = NNODES * HID / 4;   // 2,240,000
    if (i < NV) {
        float4 v = ((const float4*)xnew)[i];
        float4 o = ((float4*)out)[i];
        o.x += ALPHA * v.x; o.y += ALPHA * v.y;
        o.z += ALPHA * v.z; o.w += ALPHA * v.w;
        ((float4*)out)[i] = o;
        ((float4*)xold)[i] = make_float4(0.f, 0.f, 0.f, 0.f);
    }
}

// ---------------- launch ----------------
extern "C" void kernel_launch(void* const* d_in, const int* in_sizes, int n_in,
                              void* d_out, int out_size)
{
    const int*   eidx = (const int*)d_in[0];
    const float* feat = (const float*)d_in[1];
    const float* emb  = (const float*)d_in[2];
    const float* W1   = (const float*)d_in[3];
    const float* b1   = (const float*)d_in[4];
    const float* gm1  = (const float*)d_in[5];
    const float* be1  = (const float*)d_in[6];
    const float* W2   = (const float*)d_in[7];
    const float* b2   = (const float*)d_in[8];
    const float* gm2  = (const float*)d_in[9];
    const float* be2  = (const float*)d_in[10];
    const float* W3   = (const float*)d_in[11];
    const float* b3   = (const float*)d_in[12];
    const float* mw   = (const float*)d_in[13];
    float* out = (float*)d_out;

    const int* src = eidx;
    const int* dst = eidx + NEDGE;

    float *t1, *t2, *t3, *xa, *xb;
    cudaGetSymbolAddress((void**)&t1, g_t1);
    cudaGetSymbolAddress((void**)&t2, g_t2);
    cudaGetSymbolAddress((void**)&t3, g_t3);
    cudaGetSymbolAddress((void**)&xa, g_xa);
    cudaGetSymbolAddress((void**)&xb, g_xb);

    // ---- item metadata MLP ----
    sgemm_bias<<<dim3(H1D / 128, (NITEMS + 127) / 128), 256>>>(feat, W1, b1, t1,
                                                               NITEMS, H1D, FDIM);
    ln_relu<H1D><<<NITEMS, 128>>>(t1, gm1, be1);
    sgemm_bias<<<dim3(HID / 128, (NITEMS + 127) / 128), 256>>>(t1, W2, b2, t2,
                                                               NITEMS, HID, H1D);
    ln_relu<HID><<<NITEMS, 128>>>(t2, gm2, be2);
    sgemm_bias<<<dim3(HID / 128, (NITEMS + 127) / 128), 256>>>(t2, W3, b3, t3,
                                                               NITEMS, HID, HID);

    // ---- fuse metadata + init out, zero first propagate target ----
    build_e0<<<NNODES, 128>>>(emb, mw, out);

    // ---- edge normalization ----
    zero_deg<<<(NNODES + 255) / 256, 256>>>();
    deg_count<<<(NEDGE + 255) / 256, 256>>>(dst);
    dinv_k<<<(NNODES + 255) / 256, 256>>>();
    edge_norm<<<(NEDGE + 255) / 256, 256>>>(src, dst);

    // ---- 3 propagation layers ----
    float* xin = xa;
    float* xout = xb;
    const int prop_blocks = (int)(((size_t)NEDGE * 32 + 255) / 256);
    const int axpy_blocks = (NNODES * HID / 4 + 255) / 256;
    for (int l = 0; l < 3; ++l) {
        propagate<<<prop_blocks, 256>>>(src, dst, xin, xout);
        axpy_zero<<<axpy_blocks, 256>>>(out, xout, xin);
        float* tmp = xin; xin = xout; xout = tmp;
    }
}

// round 5
// speedup vs baseline: 1.5299x; 1.5299x over previous
#include <cuda_runtime.h>
#include <math.h>

#define NUSERS 50000
#define NITEMS 20000
#define NNODES 70000
#define FDIM   768
#define H1D    512
#define HID    128
#define NEDGE  2000000
#define ALPHA  0.25f
#define LN_EPS 1e-5f

#define SCAN_B 512
#define SCAN_G ((NNODES + SCAN_B - 1) / SCAN_B)   // 137

// ---------------- scratch ----------------
__device__ float g_t1[(size_t)NITEMS * H1D];
__device__ float g_t2[(size_t)NITEMS * HID];
__device__ float g_t3[(size_t)NITEMS * HID];
__device__ float g_xa[(size_t)NNODES * HID];
__device__ float g_xb[(size_t)NNODES * HID];
__device__ float g_dinv[NNODES];
__device__ int   g_deg[NNODES];
__device__ int   g_cur[NNODES];
__device__ int   g_offs[NNODES + 1];
__device__ int   g_bsum[SCAN_G];
__device__ int   g_boff[SCAN_G];
__device__ int   g_csrc[NEDGE];     // CSR (by dst): source node ids
__device__ float g_cw[NEDGE];       // CSR payload: dinv[src]

// ---------------- SGEMM: C = A[M,K] @ B[K,N] + bias ----------------
__global__ void sgemm_bias(const float* __restrict__ A, const float* __restrict__ B,
                           const float* __restrict__ bias, float* __restrict__ C,
                           int M, int N, int K)
{
    const int BM = 128, BN = 128, BK = 16;
    __shared__ float As[BK][BM];
    __shared__ float Bs[BK][BN];

    int tid = threadIdx.x;
    int tx = tid & 15;
    int ty = tid >> 4;
    int row0 = blockIdx.y * BM;
    int col0 = blockIdx.x * BN;

    float acc[8][8];
#pragma unroll
    for (int i = 0; i < 8; i++)
#pragma unroll
        for (int j = 0; j < 8; j++) acc[i][j] = 0.f;

    for (int k0 = 0; k0 < K; k0 += BK) {
#pragma unroll
        for (int it = 0; it < 2; ++it) {
            int idx = tid + it * 256;
            int ar = idx >> 2, ac = (idx & 3) * 4;
            int gr = row0 + ar;
            float4 av = make_float4(0.f, 0.f, 0.f, 0.f);
            if (gr < M) av = *(const float4*)(A + (size_t)gr * K + k0 + ac);
            As[ac + 0][ar] = av.x; As[ac + 1][ar] = av.y;
            As[ac + 2][ar] = av.z; As[ac + 3][ar] = av.w;
            int br = idx >> 5, bc = (idx & 31) * 4;
            float4 bv = *(const float4*)(B + (size_t)(k0 + br) * N + col0 + bc);
            *(float4*)&Bs[br][bc] = bv;
        }
        __syncthreads();

#pragma unroll
        for (int k = 0; k < BK; k++) {
            float a[8], b[8];
            *(float4*)&a[0] = *(float4*)&As[k][ty * 8];
            *(float4*)&a[4] = *(float4*)&As[k][ty * 8 + 4];
            *(float4*)&b[0] = *(float4*)&Bs[k][tx * 8];
            *(float4*)&b[4] = *(float4*)&Bs[k][tx * 8 + 4];
#pragma unroll
            for (int i = 0; i < 8; i++)
#pragma unroll
                for (int j = 0; j < 8; j++) acc[i][j] += a[i] * b[j];
        }
        __syncthreads();
    }

#pragma unroll
    for (int i = 0; i < 8; i++) {
        int gr = row0 + ty * 8 + i;
        if (gr >= M) continue;
#pragma unroll
        for (int j = 0; j < 8; j += 4) {
            int gc = col0 + tx * 8 + j;
            float4 cv;
            cv.x = acc[i][j + 0] + bias[gc + 0];
            cv.y = acc[i][j + 1] + bias[gc + 1];
            cv.z = acc[i][j + 2] + bias[gc + 2];
            cv.w = acc[i][j + 3] + bias[gc + 3];
            *(float4*)(C + (size_t)gr * N + gc) = cv;
        }
    }
}

// ---------------- LayerNorm + ReLU ----------------
template <int W>
__global__ void ln_relu(float* __restrict__ x, const float* __restrict__ g,
                        const float* __restrict__ be)
{
    constexpr int VPT = W / 128;
    int row = blockIdx.x;
    int tid = threadIdx.x;
    float* xr = x + (size_t)row * W;

    float v[VPT];
    float s = 0.f, s2 = 0.f;
#pragma unroll
    for (int i = 0; i < VPT; i++) {
        v[i] = xr[i * 128 + tid];
        s += v[i]; s2 += v[i] * v[i];
    }
#pragma unroll
    for (int o = 16; o > 0; o >>= 1) {
        s  += __shfl_xor_sync(0xffffffffu, s,  o);
        s2 += __shfl_xor_sync(0xffffffffu, s2, o);
    }
    __shared__ float rs[4], rs2[4];
    if ((tid & 31) == 0) { rs[tid >> 5] = s; rs2[tid >> 5] = s2; }
    __syncthreads();
    s  = rs[0] + rs[1] + rs[2] + rs[3];
    s2 = rs2[0] + rs2[1] + rs2[2] + rs2[3];

    float mu  = s / W;
    float var = s2 / W - mu * mu;
    float inv = 1.f / sqrtf(var + LN_EPS);
#pragma unroll
    for (int i = 0; i < VPT; i++) {
        int c = i * 128 + tid;
        float y = (v[i] - mu) * inv * g[c] + be[c];
        xr[c] = fmaxf(y, 0.f);
    }
}

// ---------------- build e0 ----------------
__global__ void build_e0(const float* __restrict__ emb, const float* __restrict__ mw,
                         float* __restrict__ out)
{
    int node = blockIdx.x;
    int tid = threadIdx.x;   // 128
    float x = emb[(size_t)node * HID + tid];
    if (node >= NUSERS) {
        int it = node - NUSERS;
        float h = g_t3[(size_t)it * HID + tid];
        float s2 = h * h;
#pragma unroll
        for (int o = 16; o > 0; o >>= 1) s2 += __shfl_xor_sync(0xffffffffu, s2, o);
        __shared__ float red[4];
        if ((tid & 31) == 0) red[tid >> 5] = s2;
        __syncthreads();
        float nrm = sqrtf(red[0] + red[1] + red[2] + red[3]);
        x += mw[0] * h / fmaxf(nrm, 1e-12f);
    }
    size_t o = (size_t)node * HID + tid;
    g_xa[o] = x;
    out[o] = ALPHA * x;
}

// ---------------- degree / dinv ----------------
__global__ void zero_deg_cur()
{
    int n = blockIdx.x * blockDim.x + threadIdx.x;
    if (n < NNODES) { g_deg[n] = 0; g_cur[n] = 0; }
}

__global__ void deg_count(const int* __restrict__ dst)
{
    int e = blockIdx.x * blockDim.x + threadIdx.x;
    if (e < NEDGE) atomicAdd(&g_deg[dst[e]], 1);
}

__global__ void dinv_k()
{
    int n = blockIdx.x * blockDim.x + threadIdx.x;
    if (n < NNODES) {
        int d = g_deg[n];
        g_dinv[n] = (d > 0) ? rsqrtf((float)d) : 0.f;
    }
}

// ---------------- exclusive scan of g_deg -> g_offs ----------------
__global__ void scan1()
{
    __shared__ int sm[SCAN_B];
    int i = blockIdx.x * SCAN_B + threadIdx.x;
    int v = (i < NNODES) ? g_deg[i] : 0;
    sm[threadIdx.x] = v;
    __syncthreads();
    // inclusive Hillis-Steele
    int val = v;
#pragma unroll
    for (int o = 1; o < SCAN_B; o <<= 1) {
        int t = (threadIdx.x >= o) ? sm[threadIdx.x - o] : 0;
        __syncthreads();
        val += t;
        sm[threadIdx.x] = val;
        __syncthreads();
    }
    if (i < NNODES) g_offs[i] = val - v;   // exclusive
    if (threadIdx.x == SCAN_B - 1) g_bsum[blockIdx.x] = val;
}

__global__ void scan2()
{
    __shared__ int sm[SCAN_G];
    int t = threadIdx.x;
    int v = (t < SCAN_G) ? g_bsum[t] : 0;
    if (t < SCAN_G) sm[t] = v;
    __syncthreads();
    if (t < SCAN_G) {
        int e = 0;
        for (int j = 0; j < t; j++) e += sm[j];   // 137 elems, 1 block: fine
        g_boff[t] = e;
    }
}

__global__ void scan3()
{
    int i = blockIdx.x * blockDim.x + threadIdx.x;
    if (i < NNODES) g_offs[i] += g_boff[i / SCAN_B];
    if (i == 0) g_offs[NNODES] = NEDGE;
}

// ---------------- scatter edges into CSR (by dst) ----------------
__global__ void scatter_edges(const int* __restrict__ src, const int* __restrict__ dst)
{
    int e = blockIdx.x * blockDim.x + threadIdx.x;
    if (e < NEDGE) {
        int s = src[e];
        int d = dst[e];
        int pos = g_offs[d] + atomicAdd(&g_cur[d], 1);
        g_csrc[pos] = s;
        g_cw[pos] = g_dinv[s];
    }
}

// ---------------- CSR propagate, fused out += alpha * xnew -------------------
// One warp per destination node; lane covers 4 contiguous floats of the row.
__global__ void propagate_csr(const float* __restrict__ xin, float* __restrict__ xout,
                              float* __restrict__ out)
{
    int node = (blockIdx.x * blockDim.x + threadIdx.x) >> 5;
    int lane = threadIdx.x & 31;
    if (node >= NNODES) return;
    int beg = g_offs[node];
    int end = g_offs[node + 1];

    float4 acc = make_float4(0.f, 0.f, 0.f, 0.f);
    int j = beg;
    for (; j + 3 < end; j += 4) {
        int   s0 = __ldg(&g_csrc[j]),     s1 = __ldg(&g_csrc[j + 1]);
        int   s2 = __ldg(&g_csrc[j + 2]), s3 = __ldg(&g_csrc[j + 3]);
        float w0 = __ldg(&g_cw[j]),       w1 = __ldg(&g_cw[j + 1]);
        float w2 = __ldg(&g_cw[j + 2]),   w3 = __ldg(&g_cw[j + 3]);
        float4 v0 = *(const float4*)(xin + (size_t)s0 * HID + lane * 4);
        float4 v1 = *(const float4*)(xin + (size_t)s1 * HID + lane * 4);
        float4 v2 = *(const float4*)(xin + (size_t)s2 * HID + lane * 4);
        float4 v3 = *(const float4*)(xin + (size_t)s3 * HID + lane * 4);
        acc.x += w0 * v0.x + w1 * v1.x + w2 * v2.x + w3 * v3.x;
        acc.y += w0 * v0.y + w1 * v1.y + w2 * v2.y + w3 * v3.y;
        acc.z += w0 * v0.z + w1 * v1.z + w2 * v2.z + w3 * v3.z;
        acc.w += w0 * v0.w + w1 * v1.w + w2 * v2.w + w3 * v3.w;
    }
    for (; j < end; ++j) {
        int   s = __ldg(&g_csrc[j]);
        float w = __ldg(&g_cw[j]);
        float4 v = *(const float4*)(xin + (size_t)s * HID + lane * 4);
        acc.x += w * v.x; acc.y += w * v.y; acc.z += w * v.z; acc.w += w * v.w;
    }

    float dn = g_dinv[node];
    acc.x *= dn; acc.y *= dn; acc.z *= dn; acc.w *= dn;

    size_t o = (size_t)node * HID + lane * 4;
    *(float4*)(xout + o) = acc;
    float4 ov = *(float4*)(out + o);
    ov.x += ALPHA * acc.x; ov.y += ALPHA * acc.y;
    ov.z += ALPHA * acc.z; ov.w += ALPHA * acc.w;
    *(float4*)(out + o) = ov;
}

// ---------------- launch ----------------
extern "C" void kernel_launch(void* const* d_in, const int* in_sizes, int n_in,
                              void* d_out, int out_size)
{
    const int*   eidx = (const int*)d_in[0];
    const float* feat = (const float*)d_in[1];
    const float* emb  = (const float*)d_in[2];
    const float* W1   = (const float*)d_in[3];
    const float* b1   = (const float*)d_in[4];
    const float* gm1  = (const float*)d_in[5];
    const float* be1  = (const float*)d_in[6];
    const float* W2   = (const float*)d_in[7];
    const float* b2   = (const float*)d_in[8];
    const float* gm2  = (const float*)d_in[9];
    const float* be2  = (const float*)d_in[10];
    const float* W3   = (const float*)d_in[11];
    const float* b3   = (const float*)d_in[12];
    const float* mw   = (const float*)d_in[13];
    float* out = (float*)d_out;

    const int* src = eidx;
    const int* dst = eidx + NEDGE;

    float *t1, *t2, *xa, *xb;
    cudaGetSymbolAddress((void**)&t1, g_t1);
    cudaGetSymbolAddress((void**)&t2, g_t2);
    cudaGetSymbolAddress((void**)&xa, g_xa);
    cudaGetSymbolAddress((void**)&xb, g_xb);
    float* t3; cudaGetSymbolAddress((void**)&t3, g_t3);

    // ---- item metadata MLP ----
    sgemm_bias<<<dim3(H1D / 128, (NITEMS + 127) / 128), 256>>>(feat, W1, b1, t1,
                                                               NITEMS, H1D, FDIM);
    ln_relu<H1D><<<NITEMS, 128>>>(t1, gm1, be1);
    sgemm_bias<<<dim3(1, (NITEMS + 127) / 128), 256>>>(t1, W2, b2, t2,
                                                       NITEMS, HID, H1D);
    ln_relu<HID><<<NITEMS, 128>>>(t2, gm2, be2);
    sgemm_bias<<<dim3(1, (NITEMS + 127) / 128), 256>>>(t2, W3, b3, t3,
                                                       NITEMS, HID, HID);

    // ---- fuse metadata + init out ----
    build_e0<<<NNODES, 128>>>(emb, mw, out);

    // ---- degree, dinv, CSR build ----
    zero_deg_cur<<<(NNODES + 255) / 256, 256>>>();
    deg_count<<<(NEDGE + 255) / 256, 256>>>(dst);
    dinv_k<<<(NNODES + 255) / 256, 256>>>();
    scan1<<<SCAN_G, SCAN_B>>>();
    scan2<<<1, 256>>>();
    scan3<<<(NNODES + 255) / 256, 256>>>();
    scatter_edges<<<(NEDGE + 255) / 256, 256>>>(src, dst);

    // ---- 3 propagation layers (fused axpy, no zeroing needed) ----
    float* xin = xa;
    float* xout = xb;
    const int prop_blocks = (int)(((size_t)NNODES * 32 + 255) / 256);
    for (int l = 0; l < 3; ++l) {
        propagate_csr<<<prop_blocks, 256>>>(xin, xout, out);
        float* tmp = xin; xin = xout; xout = tmp;
    }
}